// round 6
// baseline (speedup 1.0000x reference)
#include <cuda_runtime.h>
#include <math.h>
#include <stdint.h>

// Problem constants
#define B_  4
#define T_  2048
#define C_  1024
#define C3_ 3072
#define H_  16
#define HS_ 64
#define FF_ 4096
#define M_  (B_*T_)     // 8192 rows
#define EPS_ 1e-5f

// ---------------- scratch (no dynamic alloc allowed) ----------------
__device__ float g_h   [M_*C_];    // LN output (tf32-rounded)
__device__ float g_qkv [M_*C3_];   // fused q|k|v, row stride 3072 (tf32-rounded)
__device__ float g_o   [M_*C_];    // attention output (tf32-rounded)
__device__ float g_x1  [M_*C_];    // x + attn_out @ Wproj + bproj
__device__ float g_ff  [M_*FF_];   // relu(h2 @ W1 + b1) (tf32-rounded)
__device__ float g_wqkv[C3_*C_];   // repacked+transposed [3C, C] qkv weight
__device__ float g_wp  [C_*C_];    // transposed Wproj [N,K]
__device__ float g_w1  [FF_*C_];   // transposed W1 [4096,1024]
__device__ float g_w2  [C_*FF_];   // transposed W2 [1024,4096]

__device__ __forceinline__ uint32_t f2tf32(float f) {
    uint32_t u;
    asm("cvt.rna.tf32.f32 %0, %1;" : "=r"(u) : "f"(f));
    return u;
}
__device__ __forceinline__ float roundtf(float f) {
    return __uint_as_float(f2tf32(f));
}

__device__ __forceinline__ void mma_tf32(float* c, const uint32_t* a, const uint32_t* b) {
    asm volatile("mma.sync.aligned.m16n8k8.row.col.f32.tf32.tf32.f32 "
        "{%0,%1,%2,%3}, {%4,%5,%6,%7}, {%8,%9}, {%0,%1,%2,%3};"
        : "+f"(c[0]), "+f"(c[1]), "+f"(c[2]), "+f"(c[3])
        : "r"(a[0]), "r"(a[1]), "r"(a[2]), "r"(a[3]), "r"(b[0]), "r"(b[1]));
}
__device__ __forceinline__ uint32_t smem_u32(const void* p) {
    return (uint32_t)__cvta_generic_to_shared(p);
}

// ---------------- LayerNorm (tf32-rounded output) ----------------
__global__ __launch_bounds__(256) void ln_kernel(const float* __restrict__ x,
                                                 const float* __restrict__ g,
                                                 const float* __restrict__ b,
                                                 float* __restrict__ y)
{
    int row = blockIdx.x;
    const float* xr = x + (size_t)row * C_;
    float* yr = y + (size_t)row * C_;
    int tid = threadIdx.x;

    float s = 0.f, s2 = 0.f;
    #pragma unroll
    for (int i = tid; i < C_; i += 256) {
        float v = xr[i];
        s += v; s2 += v * v;
    }
    __shared__ float rs[256], rs2[256];
    rs[tid] = s; rs2[tid] = s2;
    __syncthreads();
    for (int off = 128; off > 0; off >>= 1) {
        if (tid < off) { rs[tid] += rs[tid+off]; rs2[tid] += rs2[tid+off]; }
        __syncthreads();
    }
    float mean = rs[0] * (1.0f / C_);
    float var  = rs2[0] * (1.0f / C_) - mean * mean;
    float rstd = rsqrtf(var + EPS_);
    #pragma unroll
    for (int i = tid; i < C_; i += 256) {
        yr[i] = roundtf((xr[i] - mean) * rstd * g[i] + b[i]);
    }
}

// ---------------- repack [H,C,HS]x3 -> [3C, C] (N rows of K), rounded --------
__global__ void repack_qkv3T(const float* __restrict__ Wq,
                             const float* __restrict__ Wk,
                             const float* __restrict__ Wv,
                             float* __restrict__ Wt)
{
    int idx = blockIdx.x * 256 + threadIdx.x;   // idx = n*C + c
    if (idx < C3_*C_) {
        int n = idx >> 10;
        int c = idx & (C_ - 1);
        int sec = n >> 10;
        int nn = n & (C_ - 1);
        int h = nn >> 6;
        int d = nn & (HS_ - 1);
        const float* W = (sec == 0) ? Wq : (sec == 1) ? Wk : Wv;
        Wt[idx] = roundtf(W[(size_t)h * C_ * HS_ + (size_t)c * HS_ + d]);
    }
}

// ---------------- transpose+round: src [R, Cc] -> dst [Cc, R] ----------------
__global__ void transpose_round(const float* __restrict__ S, float* __restrict__ D,
                                int R, int Cc)
{
    __shared__ float t[32][33];
    int bx = blockIdx.x * 32, by = blockIdx.y * 32;
    int x = threadIdx.x, y = threadIdx.y;
    #pragma unroll
    for (int i = 0; i < 32; i += 8)
        t[y + i][x] = S[(size_t)(by + y + i) * Cc + bx + x];
    __syncthreads();
    #pragma unroll
    for (int i = 0; i < 32; i += 8)
        D[(size_t)(bx + y + i) * R + by + x] = roundtf(t[x][y + i]);
}

// ---------------- tf32 mma.sync GEMM, lane-remapped float2 frags ----------------
// C[M,N] = A[M,K] @ Bt[N,K]^T (+bias)(+res)(relu)(round_out)
// 128x128 CTA tile, BK=32, 8 warps 64x32, 3-stage cp.async, 1 sync/tile.
// mma k-lane remap: lane tg <- smem col 2tg, lane tg+4 <- col 2tg+1 (both frags).
#define TSTR 36
#define G_STAGE (2*128*TSTR)      // floats per stage: A 128x36 + B 128x36
#define G_SMEM  (3*G_STAGE*4)     // 110592 bytes

__global__ __launch_bounds__(256, 2) void gemm_tf32(const float* __restrict__ A,
                                                    const float* __restrict__ Bt,
                                                    float* __restrict__ Cm,
                                                    int Mn, int Nn, int Kn,
                                                    const float* __restrict__ bias,
                                                    const float* __restrict__ res,
                                                    int relu, int round_out)
{
    extern __shared__ float smbuf[];
    const int tid = threadIdx.x;
    const int wid = tid >> 5, lane = tid & 31;
    const int g = lane >> 2, tg = lane & 3;
    const int warp_m = wid >> 2;       // 0..1
    const int warp_n = wid & 3;        // 0..3
    const int bm = blockIdx.x * 128;
    const int bn = blockIdx.y * 128;

    float acc[4][4][4];
    #pragma unroll
    for (int mi = 0; mi < 4; mi++)
        #pragma unroll
        for (int ni = 0; ni < 4; ni++)
            #pragma unroll
            for (int r = 0; r < 4; r++) acc[mi][ni][r] = 0.f;

    auto fill = [&](int s, int kt) {
        const int k0 = kt << 5;
        float* As = smbuf + s * G_STAGE;
        float* Bs = As + 128 * TSTR;
        #pragma unroll
        for (int i = 0; i < 4; i++) {
            int idx = tid + (i << 8);          // 1024 chunks each for A and B
            int r = idx >> 3, c = (idx & 7) << 2;
            uint32_t da = smem_u32(As + r * TSTR + c);
            asm volatile("cp.async.cg.shared.global [%0], [%1], 16;"
                         :: "r"(da), "l"(A + (size_t)(bm + r) * Kn + k0 + c));
            uint32_t db = smem_u32(Bs + r * TSTR + c);
            asm volatile("cp.async.cg.shared.global [%0], [%1], 16;"
                         :: "r"(db), "l"(Bt + (size_t)(bn + r) * Kn + k0 + c));
        }
        asm volatile("cp.async.commit_group;");
    };

    const int KT = Kn >> 5;
    fill(0, 0);
    fill(1, 1);

    for (int kt = 0; kt < KT; kt++) {
        if (kt < KT - 1) asm volatile("cp.async.wait_group 1;");
        else             asm volatile("cp.async.wait_group 0;");
        __syncthreads();
        if (kt + 2 < KT) fill((kt + 2) % 3, kt + 2);

        const float* As = smbuf + (kt % 3) * G_STAGE;
        const float* Bs = As + 128 * TSTR;

        #pragma unroll
        for (int ks = 0; ks < 4; ks++) {
            const int kb = ks * 8 + 2 * tg;
            uint32_t af[4][4], bf[4][2];
            #pragma unroll
            for (int mi = 0; mi < 4; mi++) {
                const float* ap = As + (warp_m * 64 + mi * 16 + g) * TSTR + kb;
                float2 lo = *(const float2*)ap;              // (a0, a2)
                float2 hi = *(const float2*)(ap + 8 * TSTR); // (a1, a3)
                af[mi][0] = __float_as_uint(lo.x);
                af[mi][1] = __float_as_uint(hi.x);
                af[mi][2] = __float_as_uint(lo.y);
                af[mi][3] = __float_as_uint(hi.y);
            }
            #pragma unroll
            for (int ni = 0; ni < 4; ni++) {
                float2 bv = *(const float2*)(Bs + (warp_n * 32 + ni * 8 + g) * TSTR + kb);
                bf[ni][0] = __float_as_uint(bv.x);
                bf[ni][1] = __float_as_uint(bv.y);
            }
            #pragma unroll
            for (int mi = 0; mi < 4; mi++)
                #pragma unroll
                for (int ni = 0; ni < 4; ni++)
                    mma_tf32(acc[mi][ni], af[mi], bf[ni]);
        }
    }

    // epilogue: c0 [g][2tg], c1 [g][2tg+1], c2/c3 at row g+8 (n-layout natural)
    #pragma unroll
    for (int mi = 0; mi < 4; mi++) {
        #pragma unroll
        for (int ni = 0; ni < 4; ni++) {
            int row0 = bm + warp_m * 64 + mi * 16 + g;
            int col  = bn + warp_n * 32 + ni * 8 + tg * 2;
            float bx = 0.f, by = 0.f;
            if (bias) { bx = bias[col]; by = bias[col + 1]; }
            #pragma unroll
            for (int half = 0; half < 2; half++) {
                int row = row0 + half * 8;
                float v0 = acc[mi][ni][half * 2 + 0] + bx;
                float v1 = acc[mi][ni][half * 2 + 1] + by;
                if (res) {
                    const float* rp = res + (size_t)row * Nn + col;
                    v0 += rp[0]; v1 += rp[1];
                }
                if (relu) { v0 = fmaxf(v0, 0.f); v1 = fmaxf(v1, 0.f); }
                if (round_out) { v0 = roundtf(v0); v1 = roundtf(v1); }
                *(float2*)(Cm + (size_t)row * Nn + col) = make_float2(v0, v1);
            }
        }
    }
}

// ---------------- tensor-core flash attention, register-resident P ----------------
// 128 queries/block, 8 warps (m16 each), 64-key tiles, 2-stage cp.async.
// Same k-lane remap; QK C-frag == PV A-frag (no P smem round-trip).
#define KSTR 68
#define VSTR 68
#define PSTR 68
#define ATTN_SMEM ((2*64*KSTR + 2*64*VSTR + 128*PSTR)*4)   // 104448

__global__ __launch_bounds__(256, 2) void attn_tc(const float* __restrict__ qkv,
                                                  float* __restrict__ o)
{
    extern __shared__ float sm[];
    float* Ks = sm;                      // 2 stages of 64 x KSTR
    float* Vs = sm + 2*64*KSTR;          // 2 stages of 64 x VSTR
    float* Ps = Vs + 2*64*VSTR;          // 128 x PSTR (Q staging, pre-scaled)

    const int tid = threadIdx.x, wid = tid >> 5, lane = tid & 31;
    const int g = lane >> 2, tg = lane & 3;
    const int qt0 = blockIdx.x * 128;
    const int h = blockIdx.y, b = blockIdx.z;

    const float* qbase = qkv + (size_t)(b * T_ + qt0) * C3_ + h * HS_;
    const float* kbase = qkv + (size_t)b * T_ * C3_ + C_  + h * HS_;
    const float* vbase = qkv + (size_t)b * T_ * C3_ + 2*C_ + h * HS_;

    // stage Q tile (128x64), pre-scaled by 1/8 (exact in tf32)
    // 256 threads: each handles half a row (32 floats = 8 float4)
    {
        int r = tid >> 1, c = (tid & 1) * 32;
        #pragma unroll
        for (int cc = 0; cc < 8; cc++) {
            float4 v = *(const float4*)(qbase + (size_t)r * C3_ + c + cc * 4);
            v.x *= 0.125f; v.y *= 0.125f; v.z *= 0.125f; v.w *= 0.125f;
            *(float4*)&Ps[r * PSTR + c + cc * 4] = v;
        }
    }

    float mrow0 = -INFINITY, mrow1 = -INFINITY, lrow0 = 0.f, lrow1 = 0.f;
    float oacc[8][4];
    #pragma unroll
    for (int j = 0; j < 8; j++)
        #pragma unroll
        for (int r = 0; r < 4; r++) oacc[j][r] = 0.f;

    const int m0 = wid * 16;
    const int r0 = qt0 + m0 + g;
    const int my_max = qt0 + m0 + 15;
    const int ntiles = (qt0 + 128) >> 6;

    auto loadKV = [&](int s, int s0) {
        const float* kp = kbase + (size_t)s0 * C3_;
        const float* vp = vbase + (size_t)s0 * C3_;
        float* Kd = Ks + s * 64 * KSTR;
        float* Vd = Vs + s * 64 * VSTR;
        #pragma unroll
        for (int i = 0; i < 4; i++) {
            int idx = tid + i * 256;
            int r = idx >> 4, c = (idx & 15) * 4;
            uint32_t dk = smem_u32(Kd + r * KSTR + c);
            asm volatile("cp.async.cg.shared.global [%0], [%1], 16;"
                         :: "r"(dk), "l"(kp + (size_t)r * C3_ + c));
            uint32_t dv = smem_u32(Vd + r * VSTR + c);
            asm volatile("cp.async.cg.shared.global [%0], [%1], 16;"
                         :: "r"(dv), "l"(vp + (size_t)r * C3_ + c));
        }
        asm volatile("cp.async.commit_group;");
    };

    loadKV(0, 0);
    __syncthreads();   // Q staging visible to all (and before first K/V compute)

    for (int t = 0; t < ntiles; t++) {
        const int s0 = t * 64;
        asm volatile("cp.async.wait_group 0;");
        __syncthreads();
        if (t + 1 < ntiles) loadKV((t + 1) & 1, s0 + 64);

        if (s0 <= my_max) {
            const float* Kt = Ks + (t & 1) * 64 * KSTR;
            const float* Vt = Vs + (t & 1) * 64 * VSTR;

            // S = (Q/8) @ K^T  (remapped float2 frags)
            float sf[8][4];
            #pragma unroll
            for (int j = 0; j < 8; j++)
                #pragma unroll
                for (int r = 0; r < 4; r++) sf[j][r] = 0.f;
            #pragma unroll
            for (int k = 0; k < 8; k++) {
                const int kb = k * 8 + 2 * tg;
                uint32_t aq[4];
                {
                    float2 lo = *(const float2*)(Ps + (m0 + g) * PSTR + kb);
                    float2 hi = *(const float2*)(Ps + (m0 + g + 8) * PSTR + kb);
                    aq[0] = __float_as_uint(lo.x);
                    aq[1] = __float_as_uint(hi.x);
                    aq[2] = __float_as_uint(lo.y);
                    aq[3] = __float_as_uint(hi.y);
                }
                #pragma unroll
                for (int j = 0; j < 8; j++) {
                    float2 kv = *(const float2*)(Kt + (j * 8 + g) * KSTR + kb);
                    uint32_t bk[2] = { __float_as_uint(kv.x), __float_as_uint(kv.y) };
                    mma_tf32(sf[j], aq, bk);
                }
            }

            // causal mask + online softmax (rows r0, r0+8); c0/c1 cols 2tg,2tg+1
            float mx0 = -INFINITY, mx1 = -INFINITY;
            #pragma unroll
            for (int j = 0; j < 8; j++) {
                int c0 = s0 + j * 8 + 2 * tg, c1 = c0 + 1;
                if (c0 > r0)     sf[j][0] = -INFINITY;
                if (c1 > r0)     sf[j][1] = -INFINITY;
                if (c0 > r0 + 8) sf[j][2] = -INFINITY;
                if (c1 > r0 + 8) sf[j][3] = -INFINITY;
                mx0 = fmaxf(mx0, fmaxf(sf[j][0], sf[j][1]));
                mx1 = fmaxf(mx1, fmaxf(sf[j][2], sf[j][3]));
            }
            mx0 = fmaxf(mx0, __shfl_xor_sync(0xffffffffu, mx0, 1));
            mx0 = fmaxf(mx0, __shfl_xor_sync(0xffffffffu, mx0, 2));
            mx1 = fmaxf(mx1, __shfl_xor_sync(0xffffffffu, mx1, 1));
            mx1 = fmaxf(mx1, __shfl_xor_sync(0xffffffffu, mx1, 2));

            float mn0 = fmaxf(mrow0, mx0), mn1 = fmaxf(mrow1, mx1);
            float corr0 = __expf(mrow0 - mn0), corr1 = __expf(mrow1 - mn1);
            float sum0 = 0.f, sum1 = 0.f;
            #pragma unroll
            for (int j = 0; j < 8; j++) {
                sf[j][0] = __expf(sf[j][0] - mn0);
                sf[j][1] = __expf(sf[j][1] - mn0);
                sf[j][2] = __expf(sf[j][2] - mn1);
                sf[j][3] = __expf(sf[j][3] - mn1);
                sum0 += sf[j][0] + sf[j][1];
                sum1 += sf[j][2] + sf[j][3];
            }
            sum0 += __shfl_xor_sync(0xffffffffu, sum0, 1);
            sum0 += __shfl_xor_sync(0xffffffffu, sum0, 2);
            sum1 += __shfl_xor_sync(0xffffffffu, sum1, 1);
            sum1 += __shfl_xor_sync(0xffffffffu, sum1, 2);
            lrow0 = lrow0 * corr0 + sum0;
            lrow1 = lrow1 * corr1 + sum1;
            mrow0 = mn0; mrow1 = mn1;
            #pragma unroll
            for (int j = 0; j < 8; j++) {
                oacc[j][0] *= corr0; oacc[j][1] *= corr0;
                oacc[j][2] *= corr1; oacc[j][3] *= corr1;
            }

            // O += P @ V : A-frag = score C-frag (in-register, tf32-rounded)
            #pragma unroll
            for (int kk = 0; kk < 8; kk++) {
                uint32_t ap[4] = { f2tf32(sf[kk][0]), f2tf32(sf[kk][2]),
                                   f2tf32(sf[kk][1]), f2tf32(sf[kk][3]) };
                const float* v0p = Vt + (kk * 8 + 2 * tg) * VSTR + g;
                #pragma unroll
                for (int jn = 0; jn < 8; jn++) {
                    uint32_t bv[2] = { __float_as_uint(v0p[jn * 8]),
                                       __float_as_uint(v0p[VSTR + jn * 8]) };
                    mma_tf32(oacc[jn], ap, bv);
                }
            }
        }
    }

    // epilogue: normalize, round, write
    float inv0 = 1.f / lrow0;
    float inv1 = 1.f / lrow1;
    float* ob0 = o + ((size_t)(b * T_ + r0)) * C_ + h * HS_;
    float* ob1 = ob0 + (size_t)8 * C_;
    #pragma unroll
    for (int j = 0; j < 8; j++) {
        int col = j * 8 + 2 * tg;
        *(float2*)(ob0 + col) = make_float2(roundtf(oacc[j][0] * inv0),
                                            roundtf(oacc[j][1] * inv0));
        *(float2*)(ob1 + col) = make_float2(roundtf(oacc[j][2] * inv1),
                                            roundtf(oacc[j][3] * inv1));
    }
}

// ---------------- launch ----------------
extern "C" void kernel_launch(void* const* d_in, const int* in_sizes, int n_in,
                              void* d_out, int out_size)
{
    const float* x     = (const float*)d_in[0];
    const float* Wq    = (const float*)d_in[1];
    const float* Wk    = (const float*)d_in[2];
    const float* Wv    = (const float*)d_in[3];
    const float* Wproj = (const float*)d_in[4];
    const float* bproj = (const float*)d_in[5];
    const float* W1    = (const float*)d_in[6];
    const float* b1    = (const float*)d_in[7];
    const float* W2    = (const float*)d_in[8];
    const float* b2    = (const float*)d_in[9];
    const float* ln1g  = (const float*)d_in[10];
    const float* ln1b  = (const float*)d_in[11];
    const float* ln2g  = (const float*)d_in[12];
    const float* ln2b  = (const float*)d_in[13];
    float* out = (float*)d_out;

    float *h, *qkv, *ob, *x1, *ff, *wqkv, *wp, *w1, *w2;
    cudaGetSymbolAddress((void**)&h,    g_h);
    cudaGetSymbolAddress((void**)&qkv,  g_qkv);
    cudaGetSymbolAddress((void**)&ob,   g_o);
    cudaGetSymbolAddress((void**)&x1,   g_x1);
    cudaGetSymbolAddress((void**)&ff,   g_ff);
    cudaGetSymbolAddress((void**)&wqkv, g_wqkv);
    cudaGetSymbolAddress((void**)&wp,   g_wp);
    cudaGetSymbolAddress((void**)&w1,   g_w1);
    cudaGetSymbolAddress((void**)&w2,   g_w2);

    cudaFuncSetAttribute(gemm_tf32, cudaFuncAttributeMaxDynamicSharedMemorySize, G_SMEM);
    cudaFuncSetAttribute(attn_tc,   cudaFuncAttributeMaxDynamicSharedMemorySize, ATTN_SMEM);

    // 1. LN1 (tf32-rounded)
    ln_kernel<<<M_, 256>>>(x, ln1g, ln1b, h);

    // 2. weight prep: repack/transpose to [N,K], tf32-rounded
    repack_qkv3T<<<(C3_*C_)/256, 256>>>(Wq, Wk, Wv, wqkv);
    dim3 tb(32, 8);
    transpose_round<<<dim3(C_/32,  C_/32),  tb>>>(Wproj, wp, C_,  C_);
    transpose_round<<<dim3(FF_/32, C_/32),  tb>>>(W1,    w1, C_,  FF_);
    transpose_round<<<dim3(C_/32,  FF_/32), tb>>>(W2,    w2, FF_, C_);

    // 3. fused QKV projection: [8192,1024] @ [1024,3072], rounded out
    gemm_tf32<<<dim3(M_/128, C3_/128), 256, G_SMEM>>>(h, wqkv, qkv, M_, C3_, C_,
                                                      nullptr, nullptr, 0, 1);

    // 4. tensor-core causal flash attention -> g_o
    dim3 ga(T_/128, H_, B_);
    attn_tc<<<ga, 256, ATTN_SMEM>>>(qkv, ob);

    // 5. x1 = x + o @ Wproj + bproj  (fp32 out)
    gemm_tf32<<<dim3(M_/128, C_/128), 256, G_SMEM>>>(ob, wp, x1, M_, C_, C_,
                                                     bproj, x, 0, 0);

    // 6. LN2 (tf32-rounded)
    ln_kernel<<<M_, 256>>>(x1, ln2g, ln2b, h);

    // 7. ff = relu(h @ W1 + b1), rounded out
    gemm_tf32<<<dim3(M_/128, FF_/128), 256, G_SMEM>>>(h, w1, ff, M_, FF_, C_,
                                                      b1, nullptr, 1, 1);

    // 8. out = x1 + ff @ W2 + b2  (final, fp32 out)
    gemm_tf32<<<dim3(M_/128, C_/128), 256, G_SMEM>>>(ff, w2, out, M_, C_, FF_,
                                                     b2, x1, 0, 0);
}

// round 7
// speedup vs baseline: 1.6520x; 1.6520x over previous
#include <cuda_runtime.h>
#include <cuda_fp16.h>
#include <math.h>
#include <stdint.h>

// Problem constants
#define B_  4
#define T_  2048
#define C_  1024
#define C3_ 3072
#define H_  16
#define HS_ 64
#define FF_ 4096
#define M_  (B_*T_)     // 8192 rows
#define EPS_ 1e-5f

// ---------------- scratch (no dynamic alloc allowed) ----------------
__device__ __half g_h   [M_*C_];    // LN output (half)
__device__ float  g_qkv [M_*C3_];   // fused q|k|v fp32 (tf32-rounded) for attention
__device__ __half g_o   [M_*C_];    // attention output (half)
__device__ float  g_x1  [M_*C_];    // x + attn_out @ Wproj + bproj (fp32)
__device__ __half g_ff  [M_*FF_];   // relu(h2 @ W1 + b1) (half)
__device__ __half g_wqkv[C3_*C_];   // repacked+transposed [3C, C] qkv weight (half)
__device__ __half g_wp  [C_*C_];    // transposed Wproj [N,K] (half)
__device__ __half g_w1  [FF_*C_];   // transposed W1 [4096,1024] (half)
__device__ __half g_w2  [C_*FF_];   // transposed W2 [1024,4096] (half)

__device__ __forceinline__ uint32_t f2tf32(float f) {
    uint32_t u;
    asm("cvt.rna.tf32.f32 %0, %1;" : "=r"(u) : "f"(f));
    return u;
}
__device__ __forceinline__ float roundtf(float f) {
    return __uint_as_float(f2tf32(f));
}

// tf32 mma (attention)
__device__ __forceinline__ void mma_tf32(float* c, const uint32_t* a, const uint32_t* b) {
    asm volatile("mma.sync.aligned.m16n8k8.row.col.f32.tf32.tf32.f32 "
        "{%0,%1,%2,%3}, {%4,%5,%6,%7}, {%8,%9}, {%0,%1,%2,%3};"
        : "+f"(c[0]), "+f"(c[1]), "+f"(c[2]), "+f"(c[3])
        : "r"(a[0]), "r"(a[1]), "r"(a[2]), "r"(a[3]), "r"(b[0]), "r"(b[1]));
}
// fp16 mma (GEMMs)
__device__ __forceinline__ void mma_fp16(float* c, const uint32_t* a, const uint32_t* b) {
    asm volatile("mma.sync.aligned.m16n8k16.row.col.f32.f16.f16.f32 "
        "{%0,%1,%2,%3}, {%4,%5,%6,%7}, {%8,%9}, {%0,%1,%2,%3};"
        : "+f"(c[0]), "+f"(c[1]), "+f"(c[2]), "+f"(c[3])
        : "r"(a[0]), "r"(a[1]), "r"(a[2]), "r"(a[3]), "r"(b[0]), "r"(b[1]));
}
__device__ __forceinline__ uint32_t smem_u32(const void* p) {
    return (uint32_t)__cvta_generic_to_shared(p);
}

// ---------------- LayerNorm: fp32 in, half out ----------------
__global__ __launch_bounds__(256) void ln_kernel(const float* __restrict__ x,
                                                 const float* __restrict__ g,
                                                 const float* __restrict__ b,
                                                 __half* __restrict__ y)
{
    int row = blockIdx.x;
    const float* xr = x + (size_t)row * C_;
    __half* yr = y + (size_t)row * C_;
    int tid = threadIdx.x;

    float s = 0.f, s2 = 0.f;
    #pragma unroll
    for (int i = tid; i < C_; i += 256) {
        float v = xr[i];
        s += v; s2 += v * v;
    }
    __shared__ float rs[256], rs2[256];
    rs[tid] = s; rs2[tid] = s2;
    __syncthreads();
    for (int off = 128; off > 0; off >>= 1) {
        if (tid < off) { rs[tid] += rs[tid+off]; rs2[tid] += rs2[tid+off]; }
        __syncthreads();
    }
    float mean = rs[0] * (1.0f / C_);
    float var  = rs2[0] * (1.0f / C_) - mean * mean;
    float rstd = rsqrtf(var + EPS_);
    #pragma unroll
    for (int i = tid; i < C_; i += 256) {
        yr[i] = __float2half_rn((xr[i] - mean) * rstd * g[i] + b[i]);
    }
}

// ---------------- repack [H,C,HS]x3 -> [3C, C] half ----------------
__global__ void repack_qkv3T(const float* __restrict__ Wq,
                             const float* __restrict__ Wk,
                             const float* __restrict__ Wv,
                             __half* __restrict__ Wt)
{
    int idx = blockIdx.x * 256 + threadIdx.x;   // idx = n*C + c
    if (idx < C3_*C_) {
        int n = idx >> 10;
        int c = idx & (C_ - 1);
        int sec = n >> 10;
        int nn = n & (C_ - 1);
        int h = nn >> 6;
        int d = nn & (HS_ - 1);
        const float* W = (sec == 0) ? Wq : (sec == 1) ? Wk : Wv;
        Wt[idx] = __float2half_rn(W[(size_t)h * C_ * HS_ + (size_t)c * HS_ + d]);
    }
}

// ---------------- transpose to half: src [R, Cc] fp32 -> dst [Cc, R] half -------
__global__ void transpose_h(const float* __restrict__ S, __half* __restrict__ D,
                            int R, int Cc)
{
    __shared__ float t[32][33];
    int bx = blockIdx.x * 32, by = blockIdx.y * 32;
    int x = threadIdx.x, y = threadIdx.y;
    #pragma unroll
    for (int i = 0; i < 32; i += 8)
        t[y + i][x] = S[(size_t)(by + y + i) * Cc + bx + x];
    __syncthreads();
    #pragma unroll
    for (int i = 0; i < 32; i += 8)
        D[(size_t)(bx + y + i) * R + by + x] = __float2half_rn(t[x][y + i]);
}

// ---------------- fp16 mma.sync GEMM ----------------
// C[M,N] = A[M,K] @ Bt[N,K]^T  (+bias)(+res)(relu)
// out_mode: 0 = fp32, 1 = fp32 tf32-rounded, 2 = half
// 128x128 CTA tile, BK=32 halves, 8 warps 64x32, 4-stage cp.async.
// Row stride 40 halves -> frag b32 loads land on banks 20g+tg: conflict-free.
#define HSTR 40
#define HG_STAGE (2*128*HSTR)          // halves per stage (A+B) = 10240
#define HG_SMEM  (4*HG_STAGE*2)        // 81920 bytes

__global__ __launch_bounds__(256, 2) void gemm_fp16(const __half* __restrict__ A,
                                                    const __half* __restrict__ Bt,
                                                    void* __restrict__ Cm,
                                                    int Mn, int Nn, int Kn,
                                                    const float* __restrict__ bias,
                                                    const float* __restrict__ res,
                                                    int relu, int out_mode)
{
    extern __shared__ __half smh[];
    const int tid = threadIdx.x;
    const int wid = tid >> 5, lane = tid & 31;
    const int g = lane >> 2, tg = lane & 3;
    const int warp_m = wid >> 2;       // 0..1
    const int warp_n = wid & 3;        // 0..3
    const int bm = blockIdx.x * 128;
    const int bn = blockIdx.y * 128;

    float acc[4][4][4];
    #pragma unroll
    for (int mi = 0; mi < 4; mi++)
        #pragma unroll
        for (int ni = 0; ni < 4; ni++)
            #pragma unroll
            for (int r = 0; r < 4; r++) acc[mi][ni][r] = 0.f;

    auto fill = [&](int s, int kt) {
        const int k0 = kt << 5;
        __half* As = smh + s * HG_STAGE;
        __half* Bs = As + 128 * HSTR;
        #pragma unroll
        for (int i = 0; i < 2; i++) {
            int idx = tid + (i << 8);          // 512 chunks of 16B (8 halves) each
            int r = idx >> 2, c8 = (idx & 3) << 3;
            uint32_t da = smem_u32(As + r * HSTR + c8);
            asm volatile("cp.async.cg.shared.global [%0], [%1], 16;"
                         :: "r"(da), "l"(A + (size_t)(bm + r) * Kn + k0 + c8));
            uint32_t db = smem_u32(Bs + r * HSTR + c8);
            asm volatile("cp.async.cg.shared.global [%0], [%1], 16;"
                         :: "r"(db), "l"(Bt + (size_t)(bn + r) * Kn + k0 + c8));
        }
        asm volatile("cp.async.commit_group;");
    };

    const int KT = Kn >> 5;
    fill(0, 0);
    fill(1, 1);
    fill(2, 2);

    for (int kt = 0; kt < KT; kt++) {
        if (kt + 2 < KT)      asm volatile("cp.async.wait_group 2;");
        else if (kt + 1 < KT) asm volatile("cp.async.wait_group 1;");
        else                  asm volatile("cp.async.wait_group 0;");
        __syncthreads();
        if (kt + 3 < KT) fill((kt + 3) & 3, kt + 3);

        const __half* As = smh + (kt & 3) * HG_STAGE;
        const __half* Bs = As + 128 * HSTR;

        #pragma unroll
        for (int ks = 0; ks < 2; ks++) {
            const int kb = ks * 16 + 2 * tg;
            uint32_t af[4][4], bf[4][2];
            #pragma unroll
            for (int mi = 0; mi < 4; mi++) {
                const __half* ap = As + (warp_m * 64 + mi * 16 + g) * HSTR + kb;
                af[mi][0] = *(const uint32_t*)ap;
                af[mi][1] = *(const uint32_t*)(ap + 8 * HSTR);
                af[mi][2] = *(const uint32_t*)(ap + 8);
                af[mi][3] = *(const uint32_t*)(ap + 8 * HSTR + 8);
            }
            #pragma unroll
            for (int ni = 0; ni < 4; ni++) {
                const __half* bp = Bs + (warp_n * 32 + ni * 8 + g) * HSTR + kb;
                bf[ni][0] = *(const uint32_t*)bp;
                bf[ni][1] = *(const uint32_t*)(bp + 8);
            }
            #pragma unroll
            for (int mi = 0; mi < 4; mi++)
                #pragma unroll
                for (int ni = 0; ni < 4; ni++)
                    mma_fp16(acc[mi][ni], af[mi], bf[ni]);
        }
    }

    // epilogue: c0/c1 = row g cols 2tg,2tg+1; c2/c3 at row g+8
    #pragma unroll
    for (int mi = 0; mi < 4; mi++) {
        #pragma unroll
        for (int ni = 0; ni < 4; ni++) {
            int row0 = bm + warp_m * 64 + mi * 16 + g;
            int col  = bn + warp_n * 32 + ni * 8 + tg * 2;
            float bx = 0.f, by = 0.f;
            if (bias) { bx = bias[col]; by = bias[col + 1]; }
            #pragma unroll
            for (int half_ = 0; half_ < 2; half_++) {
                int row = row0 + half_ * 8;
                float v0 = acc[mi][ni][half_ * 2 + 0] + bx;
                float v1 = acc[mi][ni][half_ * 2 + 1] + by;
                if (res) {
                    const float* rp = res + (size_t)row * Nn + col;
                    v0 += rp[0]; v1 += rp[1];
                }
                if (relu) { v0 = fmaxf(v0, 0.f); v1 = fmaxf(v1, 0.f); }
                if (out_mode == 2) {
                    __half2 hv = __floats2half2_rn(v0, v1);
                    *(__half2*)((__half*)Cm + (size_t)row * Nn + col) = hv;
                } else {
                    if (out_mode == 1) { v0 = roundtf(v0); v1 = roundtf(v1); }
                    *(float2*)((float*)Cm + (size_t)row * Nn + col) = make_float2(v0, v1);
                }
            }
        }
    }
}

// ---------------- tensor-core flash attention (tf32, register-resident P) -------
// fp32 qkv in, half out. 128 queries/block, 8 warps, 64-key tiles.
#define KSTR 68
#define VSTR 68
#define PSTR 68
#define ATTN_SMEM ((2*64*KSTR + 2*64*VSTR + 128*PSTR)*4)   // 104448

__global__ __launch_bounds__(256, 2) void attn_tc(const float* __restrict__ qkv,
                                                  __half* __restrict__ o)
{
    extern __shared__ float sm[];
    float* Ks = sm;                      // 2 stages of 64 x KSTR
    float* Vs = sm + 2*64*KSTR;          // 2 stages of 64 x VSTR
    float* Ps = Vs + 2*64*VSTR;          // 128 x PSTR (Q staging, pre-scaled)

    const int tid = threadIdx.x, wid = tid >> 5, lane = tid & 31;
    const int g = lane >> 2, tg = lane & 3;
    const int qt0 = blockIdx.x * 128;
    const int h = blockIdx.y, b = blockIdx.z;

    const float* qbase = qkv + (size_t)(b * T_ + qt0) * C3_ + h * HS_;
    const float* kbase = qkv + (size_t)b * T_ * C3_ + C_  + h * HS_;
    const float* vbase = qkv + (size_t)b * T_ * C3_ + 2*C_ + h * HS_;

    // stage Q tile (128x64), pre-scaled by 1/8 (exact in tf32)
    {
        int r = tid >> 1, c = (tid & 1) * 32;
        #pragma unroll
        for (int cc = 0; cc < 8; cc++) {
            float4 v = *(const float4*)(qbase + (size_t)r * C3_ + c + cc * 4);
            v.x *= 0.125f; v.y *= 0.125f; v.z *= 0.125f; v.w *= 0.125f;
            *(float4*)&Ps[r * PSTR + c + cc * 4] = v;
        }
    }

    float mrow0 = -INFINITY, mrow1 = -INFINITY, lrow0 = 0.f, lrow1 = 0.f;
    float oacc[8][4];
    #pragma unroll
    for (int j = 0; j < 8; j++)
        #pragma unroll
        for (int r = 0; r < 4; r++) oacc[j][r] = 0.f;

    const int m0 = wid * 16;
    const int r0 = qt0 + m0 + g;
    const int my_max = qt0 + m0 + 15;
    const int ntiles = (qt0 + 128) >> 6;

    auto loadKV = [&](int s, int s0) {
        const float* kp = kbase + (size_t)s0 * C3_;
        const float* vp = vbase + (size_t)s0 * C3_;
        float* Kd = Ks + s * 64 * KSTR;
        float* Vd = Vs + s * 64 * VSTR;
        #pragma unroll
        for (int i = 0; i < 4; i++) {
            int idx = tid + i * 256;
            int r = idx >> 4, c = (idx & 15) * 4;
            uint32_t dk = smem_u32(Kd + r * KSTR + c);
            asm volatile("cp.async.cg.shared.global [%0], [%1], 16;"
                         :: "r"(dk), "l"(kp + (size_t)r * C3_ + c));
            uint32_t dv = smem_u32(Vd + r * VSTR + c);
            asm volatile("cp.async.cg.shared.global [%0], [%1], 16;"
                         :: "r"(dv), "l"(vp + (size_t)r * C3_ + c));
        }
        asm volatile("cp.async.commit_group;");
    };

    loadKV(0, 0);
    __syncthreads();   // Q staging visible (and ordered before first compute)

    for (int t = 0; t < ntiles; t++) {
        const int s0 = t * 64;
        asm volatile("cp.async.wait_group 0;");
        __syncthreads();
        if (t + 1 < ntiles) loadKV((t + 1) & 1, s0 + 64);

        if (s0 <= my_max) {
            const float* Kt = Ks + (t & 1) * 64 * KSTR;
            const float* Vt = Vs + (t & 1) * 64 * VSTR;

            // S = (Q/8) @ K^T  (k-lane remap sigma(tg)=2tg)
            float sf[8][4];
            #pragma unroll
            for (int j = 0; j < 8; j++)
                #pragma unroll
                for (int r = 0; r < 4; r++) sf[j][r] = 0.f;
            #pragma unroll
            for (int k = 0; k < 8; k++) {
                const int kb = k * 8 + 2 * tg;
                uint32_t aq[4];
                {
                    float2 lo = *(const float2*)(Ps + (m0 + g) * PSTR + kb);
                    float2 hi = *(const float2*)(Ps + (m0 + g + 8) * PSTR + kb);
                    aq[0] = __float_as_uint(lo.x);
                    aq[1] = __float_as_uint(hi.x);
                    aq[2] = __float_as_uint(lo.y);
                    aq[3] = __float_as_uint(hi.y);
                }
                #pragma unroll
                for (int j = 0; j < 8; j++) {
                    float2 kv = *(const float2*)(Kt + (j * 8 + g) * KSTR + kb);
                    uint32_t bk[2] = { __float_as_uint(kv.x), __float_as_uint(kv.y) };
                    mma_tf32(sf[j], aq, bk);
                }
            }

            // causal mask + online softmax
            float mx0 = -INFINITY, mx1 = -INFINITY;
            #pragma unroll
            for (int j = 0; j < 8; j++) {
                int c0 = s0 + j * 8 + 2 * tg, c1 = c0 + 1;
                if (c0 > r0)     sf[j][0] = -INFINITY;
                if (c1 > r0)     sf[j][1] = -INFINITY;
                if (c0 > r0 + 8) sf[j][2] = -INFINITY;
                if (c1 > r0 + 8) sf[j][3] = -INFINITY;
                mx0 = fmaxf(mx0, fmaxf(sf[j][0], sf[j][1]));
                mx1 = fmaxf(mx1, fmaxf(sf[j][2], sf[j][3]));
            }
            mx0 = fmaxf(mx0, __shfl_xor_sync(0xffffffffu, mx0, 1));
            mx0 = fmaxf(mx0, __shfl_xor_sync(0xffffffffu, mx0, 2));
            mx1 = fmaxf(mx1, __shfl_xor_sync(0xffffffffu, mx1, 1));
            mx1 = fmaxf(mx1, __shfl_xor_sync(0xffffffffu, mx1, 2));

            float mn0 = fmaxf(mrow0, mx0), mn1 = fmaxf(mrow1, mx1);
            float corr0 = __expf(mrow0 - mn0), corr1 = __expf(mrow1 - mn1);
            float sum0 = 0.f, sum1 = 0.f;
            #pragma unroll
            for (int j = 0; j < 8; j++) {
                sf[j][0] = __expf(sf[j][0] - mn0);
                sf[j][1] = __expf(sf[j][1] - mn0);
                sf[j][2] = __expf(sf[j][2] - mn1);
                sf[j][3] = __expf(sf[j][3] - mn1);
                sum0 += sf[j][0] + sf[j][1];
                sum1 += sf[j][2] + sf[j][3];
            }
            sum0 += __shfl_xor_sync(0xffffffffu, sum0, 1);
            sum0 += __shfl_xor_sync(0xffffffffu, sum0, 2);
            sum1 += __shfl_xor_sync(0xffffffffu, sum1, 1);
            sum1 += __shfl_xor_sync(0xffffffffu, sum1, 2);
            lrow0 = lrow0 * corr0 + sum0;
            lrow1 = lrow1 * corr1 + sum1;
            mrow0 = mn0; mrow1 = mn1;
            #pragma unroll
            for (int j = 0; j < 8; j++) {
                oacc[j][0] *= corr0; oacc[j][1] *= corr0;
                oacc[j][2] *= corr1; oacc[j][3] *= corr1;
            }

            // O += P @ V : A-frag = score C-frag (in-register, tf32-rounded)
            #pragma unroll
            for (int kk = 0; kk < 8; kk++) {
                uint32_t ap[4] = { f2tf32(sf[kk][0]), f2tf32(sf[kk][2]),
                                   f2tf32(sf[kk][1]), f2tf32(sf[kk][3]) };
                const float* v0p = Vt + (kk * 8 + 2 * tg) * VSTR + g;
                #pragma unroll
                for (int jn = 0; jn < 8; jn++) {
                    uint32_t bv[2] = { __float_as_uint(v0p[jn * 8]),
                                       __float_as_uint(v0p[VSTR + jn * 8]) };
                    mma_tf32(oacc[jn], ap, bv);
                }
            }
        }
    }

    // epilogue: normalize, write half (feeds proj GEMM)
    float inv0 = 1.f / lrow0;
    float inv1 = 1.f / lrow1;
    __half* ob0 = o + ((size_t)(b * T_ + r0)) * C_ + h * HS_;
    __half* ob1 = ob0 + (size_t)8 * C_;
    #pragma unroll
    for (int j = 0; j < 8; j++) {
        int col = j * 8 + 2 * tg;
        *(__half2*)(ob0 + col) = __floats2half2_rn(oacc[j][0] * inv0, oacc[j][1] * inv0);
        *(__half2*)(ob1 + col) = __floats2half2_rn(oacc[j][2] * inv1, oacc[j][3] * inv1);
    }
}

// ---------------- launch ----------------
extern "C" void kernel_launch(void* const* d_in, const int* in_sizes, int n_in,
                              void* d_out, int out_size)
{
    const float* x     = (const float*)d_in[0];
    const float* Wq    = (const float*)d_in[1];
    const float* Wk    = (const float*)d_in[2];
    const float* Wv    = (const float*)d_in[3];
    const float* Wproj = (const float*)d_in[4];
    const float* bproj = (const float*)d_in[5];
    const float* W1    = (const float*)d_in[6];
    const float* b1    = (const float*)d_in[7];
    const float* W2    = (const float*)d_in[8];
    const float* b2    = (const float*)d_in[9];
    const float* ln1g  = (const float*)d_in[10];
    const float* ln1b  = (const float*)d_in[11];
    const float* ln2g  = (const float*)d_in[12];
    const float* ln2b  = (const float*)d_in[13];
    float* out = (float*)d_out;

    __half *h, *ob, *ff, *wqkv, *wp, *w1, *w2;
    float *qkv, *x1;
    cudaGetSymbolAddress((void**)&h,    g_h);
    cudaGetSymbolAddress((void**)&qkv,  g_qkv);
    cudaGetSymbolAddress((void**)&ob,   g_o);
    cudaGetSymbolAddress((void**)&x1,   g_x1);
    cudaGetSymbolAddress((void**)&ff,   g_ff);
    cudaGetSymbolAddress((void**)&wqkv, g_wqkv);
    cudaGetSymbolAddress((void**)&wp,   g_wp);
    cudaGetSymbolAddress((void**)&w1,   g_w1);
    cudaGetSymbolAddress((void**)&w2,   g_w2);

    cudaFuncSetAttribute(gemm_fp16, cudaFuncAttributeMaxDynamicSharedMemorySize, HG_SMEM);
    cudaFuncSetAttribute(attn_tc,   cudaFuncAttributeMaxDynamicSharedMemorySize, ATTN_SMEM);

    // 1. LN1 -> half
    ln_kernel<<<M_, 256>>>(x, ln1g, ln1b, h);

    // 2. weight prep: repack/transpose to [N,K] half
    repack_qkv3T<<<(C3_*C_)/256, 256>>>(Wq, Wk, Wv, wqkv);
    dim3 tb(32, 8);
    transpose_h<<<dim3(C_/32,  C_/32),  tb>>>(Wproj, wp, C_,  C_);
    transpose_h<<<dim3(FF_/32, C_/32),  tb>>>(W1,    w1, C_,  FF_);
    transpose_h<<<dim3(C_/32,  FF_/32), tb>>>(W2,    w2, FF_, C_);

    // 3. fused QKV projection -> fp32 (tf32-rounded) for attention
    gemm_fp16<<<dim3(M_/128, C3_/128), 256, HG_SMEM>>>(h, wqkv, qkv, M_, C3_, C_,
                                                       nullptr, nullptr, 0, 1);

    // 4. tf32 causal flash attention -> half g_o
    dim3 ga(T_/128, H_, B_);
    attn_tc<<<ga, 256, ATTN_SMEM>>>(qkv, ob);

    // 5. x1 = x + o @ Wproj + bproj  (fp32 out)
    gemm_fp16<<<dim3(M_/128, C_/128), 256, HG_SMEM>>>(ob, wp, x1, M_, C_, C_,
                                                      bproj, x, 0, 0);

    // 6. LN2 -> half
    ln_kernel<<<M_, 256>>>(x1, ln2g, ln2b, h);

    // 7. ff = relu(h @ W1 + b1) -> half
    gemm_fp16<<<dim3(M_/128, FF_/128), 256, HG_SMEM>>>(h, w1, ff, M_, FF_, C_,
                                                       b1, nullptr, 1, 2);

    // 8. out = x1 + ff @ W2 + b2  (final, fp32 out)
    gemm_fp16<<<dim3(M_/128, C_/128), 256, HG_SMEM>>>(ff, w2, out, M_, C_, FF_,
                                                      b2, x1, 0, 0);
}